// round 10
// baseline (speedup 1.0000x reference)
#include <cuda_runtime.h>
#include <cstdint>

// Problem constants
#define BB   64
#define TT   2048
#define II   200
#define HH   100
#define G4   400   // 4*H

// Scratch: xg[t][b][j] (t-major so scan streams coalesced rows), ~210MB.
__device__ float g_xg[(size_t)TT * BB * G4];

// ---- packed fp32x2 helpers ---------------------------------------------
union f2u { float2 f; unsigned long long u; };
union f4u { float4 f; ulonglong2 u; };

__device__ __forceinline__ unsigned long long ffma2(unsigned long long a,
                                                    unsigned long long b,
                                                    unsigned long long c) {
    unsigned long long d;
    asm("fma.rn.f32x2 %0, %1, %2, %3;" : "=l"(d) : "l"(a), "l"(b), "l"(c));
    return d;
}
__device__ __forceinline__ unsigned long long fadd2(unsigned long long a,
                                                    unsigned long long b) {
    unsigned long long d;
    asm("add.rn.f32x2 %0, %1, %2;" : "=l"(d) : "l"(a), "l"(b));
    return d;
}
__device__ __forceinline__ float tanh_mufu(float x) {
    float t;
    asm("tanh.approx.f32 %0, %1;" : "=f"(t) : "f"(x));
    return t;
}
// branch-free activation: is_t -> tanh, else sigmoid = 0.5*tanh(x/2)+0.5
__device__ __forceinline__ float act_(float x, bool is_t) {
    float xx = is_t ? x : 0.5f * x;
    float t  = tanh_mufu(xx);
    return is_t ? t : fmaf(0.5f, t, 0.5f);
}

// ---- kernel 1: input projection (register-blocked SIMT GEMM) -----------
// C[131072, 400] = x[131072, 200] @ W_ih^T  (+bias) -> g_xg[t][b][col]
// CTA tile: 64 rows x 100 cols (grid 2048 x 4). 200 threads, thread tile 8x4.
#define KC 20
#define AS_STRIDE 68   // 68*4=272B, 16B aligned

__global__ __launch_bounds__(200, 4)
void proj_kernel(const float* __restrict__ x,
                 const float* __restrict__ Wih,
                 const float* __restrict__ bih,
                 const float* __restrict__ bhh) {
    __shared__ float As[KC * AS_STRIDE];   // As[k][r], 5.44 KB
    __shared__ float Bs[KC * HH];          // Bs[k][jc], 8 KB

    const int tid  = threadIdx.x;
    const int tx   = tid % 25;             // col group: cols tx*4 .. tx*4+3
    const int ty   = tid / 25;             // row group: rows ty*8 .. ty*8+7
    const int row0 = blockIdx.x * 64;
    const int c0   = blockIdx.y * HH;      // global column base (0/100/200/300)

    unsigned long long acc[8][2];
    #pragma unroll
    for (int r = 0; r < 8; ++r) { acc[r][0] = 0ULL; acc[r][1] = 0ULL; }

    for (int cch = 0; cch < II / KC; ++cch) {
        const int k0 = cch * KC;
        __syncthreads();   // previous chunk fully consumed

        // Stage A: 64 rows x 20 k, transposed to As[k][r]. 320 float4 loads.
        for (int idx = tid; idx < 64 * (KC / 4); idx += 200) {
            int r = idx / (KC / 4);
            int q = idx - r * (KC / 4);
            float4 v = *(const float4*)&x[(size_t)(row0 + r) * II + k0 + 4 * q];
            As[(4 * q + 0) * AS_STRIDE + r] = v.x;
            As[(4 * q + 1) * AS_STRIDE + r] = v.y;
            As[(4 * q + 2) * AS_STRIDE + r] = v.z;
            As[(4 * q + 3) * AS_STRIDE + r] = v.w;
        }
        // Stage B (transposing): thread t<100 owns W_ih row j=c0+t (L2-resident)
        if (tid < HH) {
            const float* wrow = &Wih[(size_t)(c0 + tid) * II + k0];
            #pragma unroll
            for (int q = 0; q < KC / 4; ++q) {
                float4 v = *(const float4*)&wrow[4 * q];
                Bs[(4 * q + 0) * HH + tid] = v.x;
                Bs[(4 * q + 1) * HH + tid] = v.y;
                Bs[(4 * q + 2) * HH + tid] = v.z;
                Bs[(4 * q + 3) * HH + tid] = v.w;
            }
        }
        __syncthreads();

        #pragma unroll 4
        for (int k = 0; k < KC; ++k) {
            f4u a0, a1, w0;
            a0.f = *(const float4*)&As[k * AS_STRIDE + ty * 8];
            a1.f = *(const float4*)&As[k * AS_STRIDE + ty * 8 + 4];
            w0.f = *(const float4*)&Bs[k * HH + tx * 4];
            float ar[8] = {a0.f.x, a0.f.y, a0.f.z, a0.f.w,
                           a1.f.x, a1.f.y, a1.f.z, a1.f.w};
            #pragma unroll
            for (int r = 0; r < 8; ++r) {
                f2u av; av.f.x = ar[r]; av.f.y = ar[r];
                acc[r][0] = ffma2(av.u, w0.u.x, acc[r][0]);
                acc[r][1] = ffma2(av.u, w0.u.y, acc[r][1]);
            }
        }
    }

    // Epilogue: add bias, scatter rows to g_xg[t][b][col]
    const int col = c0 + tx * 4;
    f4u bi, bh;
    bi.f = *(const float4*)&bih[col];
    bh.f = *(const float4*)&bhh[col];
    float4 bias = make_float4(bi.f.x + bh.f.x, bi.f.y + bh.f.y,
                              bi.f.z + bh.f.z, bi.f.w + bh.f.w);

    #pragma unroll
    for (int r = 0; r < 8; ++r) {
        int m = row0 + ty * 8 + r;
        int b = m >> 11;           // m / 2048
        int t = m & 2047;
        f2u p0, p1;
        p0.u = acc[r][0]; p1.u = acc[r][1];
        float4 o = make_float4(p0.f.x + bias.x, p0.f.y + bias.y,
                               p1.f.x + bias.z, p1.f.y + bias.w);
        *(float4*)&g_xg[((size_t)t * BB + b) * G4 + col] = o;
    }
}

// ---- kernel 2: sequential LSTM scan, TWO batches per CTA ----------------
// 32 CTAs x 400 threads. CTA k handles batches k and k+32; thread quad
// 4j..4j+3 owns gates i,f,g,o of unit j for BOTH batches, reusing the same
// W_hh registers. Per step: two independent dot products (4 FFMA2 chains),
// ONE barrier covering both h updates -> tail/chain/barrier exposure
// amortized 2x at constant weight-register cost. h double-buffered.
// Activations use MUFU.TANH. xg prefetched 2 steps ahead per batch.
__global__ __launch_bounds__(400, 1)
void scan_kernel(const float* __restrict__ Whh, float* __restrict__ out) {
    const int cta  = blockIdx.x;        // 0..31
    const int tid  = threadIdx.x;
    const int j    = tid >> 2;          // hidden unit 0..99
    const int g    = tid & 3;           // gate: 0=i 1=f 2=g 3=o
    const int lane = tid & 31;
    const unsigned qmask = 0xFu << (lane & ~3);

    __shared__ __align__(16) float h_sh[2][2][HH];   // [phase][batch][unit]

    // W_hh row (g*100 + j) in registers: 25 float4 (shared by both batches)
    f4u wreg[HH / 4];
    const float4* wr = (const float4*)(Whh + (size_t)(g * HH + j) * HH);
    #pragma unroll
    for (int q = 0; q < HH / 4; ++q) wreg[q].f = wr[q];

    float cA = 0.0f, cB = 0.0f, hA = 0.0f, hB = 0.0f;
    if (tid < HH) { h_sh[0][0][tid] = 0.0f; h_sh[0][1][tid] = 0.0f; }
    __syncthreads();

    const float* xgA = g_xg + (size_t)cta        * G4 + (g * HH + j);
    const float* xgB = g_xg + (size_t)(cta + 32) * G4 + (g * HH + j);
    const size_t ts = (size_t)BB * G4;

    float curA[2], curB[2], nxtA[2], nxtB[2];
    curA[0] = __ldcs(&xgA[0]);  curA[1] = __ldcs(&xgA[ts]);
    curB[0] = __ldcs(&xgB[0]);  curB[1] = __ldcs(&xgB[ts]);

    int p = 0;
    for (int tg = 0; tg < TT; tg += 2) {
        // prefetch steps tg+2, tg+3 for both batches
        int t2 = tg + 2; t2 = (t2 < TT) ? t2 : (TT - 1);
        int t3 = tg + 3; t3 = (t3 < TT) ? t3 : (TT - 1);
        nxtA[0] = __ldcs(&xgA[(size_t)t2 * ts]);
        nxtA[1] = __ldcs(&xgA[(size_t)t3 * ts]);
        nxtB[0] = __ldcs(&xgB[(size_t)t2 * ts]);
        nxtB[1] = __ldcs(&xgB[(size_t)t3 * ts]);

        #pragma unroll
        for (int i = 0; i < 2; ++i) {
            unsigned long long A0 = 0ULL, A1 = 0ULL, B0 = 0ULL, B1 = 0ULL;
            const float4* hbA = (const float4*)h_sh[p][0];
            const float4* hbB = (const float4*)h_sh[p][1];
            #pragma unroll
            for (int q = 0; q < HH / 4; ++q) {
                f4u ha; ha.f = hbA[q];          // broadcast LDS.128
                f4u hb; hb.f = hbB[q];
                A0 = ffma2(wreg[q].u.x, ha.u.x, A0);
                A1 = ffma2(wreg[q].u.y, ha.u.y, A1);
                B0 = ffma2(wreg[q].u.x, hb.u.x, B0);
                B1 = ffma2(wreg[q].u.y, hb.u.y, B1);
            }
            f2u sA, sB;
            sA.u = fadd2(A0, A1);
            sB.u = fadd2(B0, B1);
            float gateA = (sA.f.x + sA.f.y) + curA[i];
            float gateB = (sB.f.x + sB.f.y) + curB[i];

            const bool is_t = (g == 2);
            float aA = act_(gateA, is_t);
            float aB = act_(gateB, is_t);

            // quad combine for both batches (leader-only tail)
            float fA = __shfl_down_sync(qmask, aA, 1, 4);
            float gA = __shfl_down_sync(qmask, aA, 2, 4);
            float oA = __shfl_down_sync(qmask, aA, 3, 4);
            float fB = __shfl_down_sync(qmask, aB, 1, 4);
            float gB = __shfl_down_sync(qmask, aB, 2, 4);
            float oB = __shfl_down_sync(qmask, aB, 3, 4);
            if (g == 0) {
                cA = fA * cA + aA * gA;
                hA = oA * tanh_mufu(cA);
                h_sh[p ^ 1][0][j] = hA;
                cB = fB * cB + aB * gB;
                hB = oB * tanh_mufu(cB);
                h_sh[p ^ 1][1][j] = hB;
            }
            __syncthreads();
            p ^= 1;
        }

        curA[0] = nxtA[0]; curA[1] = nxtA[1];
        curB[0] = nxtB[0]; curB[1] = nxtB[1];
    }

    if (g == 0) {
        out[cta * HH + j]        = hA;
        out[(cta + 32) * HH + j] = hB;
    }
}

// ---- launch ------------------------------------------------------------
extern "C" void kernel_launch(void* const* d_in, const int* in_sizes, int n_in,
                              void* d_out, int out_size) {
    const float* x   = (const float*)d_in[0];   // [64,2048,200]
    const float* Wih = (const float*)d_in[1];   // [400,200]
    const float* Whh = (const float*)d_in[2];   // [400,100]
    const float* bih = (const float*)d_in[3];   // [400]
    const float* bhh = (const float*)d_in[4];   // [400]
    float* out = (float*)d_out;                 // [64,100]

    proj_kernel<<<dim3(TT / 64 * BB / 64 * 64, 4), 200>>>(x, Wih, bih, bhh);
    scan_kernel<<<BB / 2, 400>>>(Whh, out);
}